// round 12
// baseline (speedup 1.0000x reference)
#include <cuda_runtime.h>
#include <cstdint>

// DistanceLoss: out[b,n] = min_m ||input[b,n,:] - point[b,m,:]||^2
// B=4, N=8192, M=8192, D=3 (float32), inputs iid N(0,1).
//
// R12: exact nearest-neighbor with 1-D slab pruning (replaces brute force).
//  - 32 x-slabs at standard-normal quantiles (hardcoded, strictly increasing;
//    accuracy of the constants affects only load balance, never correctness).
//  - Points and queries bucketed per (batch, slab) via atomicAdd scatter into
//    __device__ scratch (capacity 512 = mean 256 + 16 sigma; unreachable).
//  - NN kernel: one block per (batch, slab, part). All lanes' queries share the
//    slab, so slab expansion is warp-collective: a side is closed only when
//    EVERY lane votes gap^2 >= its own best (__all_sync) — exact per-lane
//    bound, warp-uniform control flow. Point loads are warp-uniform addresses
//    (broadcast, L1/L2 resident).
//  - Each query's result written exactly once with a plain store (no atomics,
//    no output-init kernel). Scatter order nondeterminism is harmless: min
//    over the same set is order-independent -> deterministic output.

#define BB     4
#define NQ     8192
#define MP     8192
#define NSLAB  32
#define PCAP   512
#define QCAP   512
#define NPART  2
#define TPB    128

// cE[s] .. cE[s+1] bounds slab s. cE[0]/cE[32] are +-inf sentinels.
__constant__ float cE[33] = {
    -1e30f,
    -1.8627f, -1.5341f, -1.3180f, -1.1503f, -1.0100f, -0.8871f, -0.7764f,
    -0.6745f, -0.5791f, -0.4888f, -0.4023f, -0.3186f, -0.2372f, -0.1573f,
    -0.0784f,  0.0000f,  0.0784f,  0.1573f,  0.2372f,  0.3186f,  0.4023f,
     0.4888f,  0.5791f,  0.6745f,  0.7764f,  0.8871f,  1.0100f,  1.1503f,
     1.3180f,  1.5341f,  1.8627f,
     1e30f
};

__device__ int    g_pcnt[BB * NSLAB];
__device__ int    g_qcnt[BB * NSLAB];
__device__ float4 g_pts[BB * NSLAB * PCAP];   // (x, y, z, 0)
__device__ float4 g_qs [BB * NSLAB * QCAP];   // (x, y, z, bitcast(n))

__global__ void k_zero() {
    int i = threadIdx.x;
    if (i < BB * NSLAB) { g_pcnt[i] = 0; g_qcnt[i] = 0; }
}

__device__ __forceinline__ int slab_of(float x) {
    int s = 0;
    #pragma unroll
    for (int k = 1; k <= 31; k++) s += (x >= cE[k]) ? 1 : 0;
    return s;
}

__global__ void k_scatter_p(const float* __restrict__ pnt) {
    int i = blockIdx.x * blockDim.x + threadIdx.x;   // 0 .. BB*MP-1
    int b = i >> 13;
    const float* p = pnt + (size_t)i * 3;
    float x = p[0], y = p[1], z = p[2];
    int s = slab_of(x);
    int pos = atomicAdd(&g_pcnt[b * NSLAB + s], 1);
    if (pos < PCAP)
        g_pts[(b * NSLAB + s) * PCAP + pos] = make_float4(x, y, z, 0.f);
}

__global__ void k_scatter_q(const float* __restrict__ inp) {
    int i = blockIdx.x * blockDim.x + threadIdx.x;   // 0 .. BB*NQ-1
    int b = i >> 13, n = i & (NQ - 1);
    const float* q = inp + (size_t)i * 3;
    float x = q[0], y = q[1], z = q[2];
    int s = slab_of(x);
    int pos = atomicAdd(&g_qcnt[b * NSLAB + s], 1);
    if (pos < QCAP)
        g_qs[(b * NSLAB + s) * QCAP + pos] = make_float4(x, y, z, __int_as_float(n));
}

__device__ __forceinline__ float scan_slab(int b, int s,
                                           float qx, float qy, float qz,
                                           float best) {
    int n = g_pcnt[b * NSLAB + s];
    if (n > PCAP) n = PCAP;
    const float4* base = g_pts + (b * NSLAB + s) * PCAP;
    #pragma unroll 4
    for (int j = 0; j < n; j++) {
        float4 p = base[j];                       // warp-uniform address: broadcast
        float dx = qx - p.x, dy = qy - p.y, dz = qz - p.z;
        float d = fmaf(dz, dz, fmaf(dy, dy, dx * dx));
        best = fminf(best, d);
    }
    return best;
}

__global__ __launch_bounds__(TPB)
void k_nn(float* __restrict__ out) {
    const int b    = blockIdx.y;
    const int slab = blockIdx.x / NPART;
    const int part = blockIdx.x % NPART;

    int nq = g_qcnt[b * NSLAB + slab];
    if (nq > QCAP) nq = QCAP;
    int chunk = (nq + NPART - 1) / NPART;
    int qs = part * chunk;
    int qe = min(nq, qs + chunk);
    int rounds = (qe - qs + TPB - 1) / TPB;       // block-uniform

    for (int rd = 0; rd < rounds; rd++) {
        int qi = qs + rd * TPB + threadIdx.x;
        bool act = qi < qe;
        float4 q = act ? g_qs[(b * NSLAB + slab) * QCAP + qi]
                       : make_float4(0.f, 0.f, 0.f, 0.f);
        // Inactive lanes: best = 0 -> every skip vote passes, no effect.
        float best = act ? 3.4e38f : 0.f;

        best = scan_slab(b, slab, q.x, q.y, q.z, best);

        int l = slab - 1, r = slab + 1;
        for (;;) {
            bool canL = false, canR = false;
            if (l >= 0) {                          // warp-uniform condition
                float g = q.x - cE[l + 1];         // >= 0 for active lanes
                canL = !__all_sync(0xffffffffu, g * g >= best);
            }
            if (r <= 31) {
                float g = cE[r] - q.x;
                canR = !__all_sync(0xffffffffu, g * g >= best);
            }
            int s;
            if (canL && canR)
                s = ((cE[slab] - cE[l + 1]) <= (cE[r] - cE[slab + 1]))
                        ? (l--) : (r++);
            else if (canL) s = l--;
            else if (canR) s = r++;
            else break;
            best = scan_slab(b, s, q.x, q.y, q.z, best);
        }

        if (act) out[b * NQ + __float_as_int(q.w)] = best;
    }
}

extern "C" void kernel_launch(void* const* d_in, const int* in_sizes, int n_in,
                              void* d_out, int out_size) {
    const float* inp = (const float*)d_in[0];   // [B, N, 3] queries
    const float* pnt = (const float*)d_in[1];   // [B, M, 3] points
    float* out = (float*)d_out;                 // [B, N]

    k_zero<<<1, 128>>>();
    k_scatter_p<<<(BB * MP) / TPB, TPB>>>(pnt);
    k_scatter_q<<<(BB * NQ) / TPB, TPB>>>(inp);
    k_nn<<<dim3(NSLAB * NPART, BB), TPB>>>(out);
}

// round 13
// speedup vs baseline: 4.4687x; 4.4687x over previous
#include <cuda_runtime.h>
#include <cstdint>

// DistanceLoss: out[b,n] = min_m ||input[b,n,:] - point[b,m,:]||^2
// B=4, N=8192, M=8192, D=3 (float32), inputs iid N(0,1).
//
// R13: slab pruning (R12) fused with the dense FFMA2 engine (R5).
//  - 32 x-slabs at normal quantiles; points scattered to per-(b,slab) arrays
//    as (x,y,z,c) with c = -0.5*|p|^2; queries scattered likewise.
//  - NN: one block per (b, slab, half). The block walks slabs together
//    (block-uniform control); each visited slab is tiled into smem pair-packed
//    and scanned with the R5 FFMA2 loop (2 queries/thread, 2 points/group).
//  - Exact pruning: side skipped only when EVERY query in the block has
//    gap^2 >= sq - 2*max  (== current best d^2); sides never reopen.
//  - Results stored once, plain STG. Scatter order nondeterminism harmless
//    (min over a fixed set). Capacity 512 vs mean 256 (+16 sigma): safe.

#define BB     4
#define NQ     8192
#define MP     8192
#define NSLAB  32
#define PCAP   512
#define QCAP   512
#define NPART  2
#define TPB    128
#define MAXGRP (PCAP / 2)   // 256 groups -> 8 KB smem

typedef unsigned long long u64;

__constant__ float cE[33] = {
    -1e30f,
    -1.8627f, -1.5341f, -1.3180f, -1.1503f, -1.0100f, -0.8871f, -0.7764f,
    -0.6745f, -0.5791f, -0.4888f, -0.4023f, -0.3186f, -0.2372f, -0.1573f,
    -0.0784f,  0.0000f,  0.0784f,  0.1573f,  0.2372f,  0.3186f,  0.4023f,
     0.4888f,  0.5791f,  0.6745f,  0.7764f,  0.8871f,  1.0100f,  1.1503f,
     1.3180f,  1.5341f,  1.8627f,
     1e30f
};

__device__ int    g_pcnt[BB * NSLAB];
__device__ int    g_qcnt[BB * NSLAB];
__device__ float4 g_pts[BB * NSLAB * PCAP];   // (x, y, z, -0.5|p|^2)
__device__ float4 g_qs [BB * NSLAB * QCAP];   // (x, y, z, bitcast(n))

__device__ __forceinline__ u64 pack2(float lo, float hi) {
    u64 r;
    asm("mov.b64 %0, {%1, %2};" : "=l"(r) : "f"(lo), "f"(hi));
    return r;
}
__device__ __forceinline__ void unpack2(u64 v, float& lo, float& hi) {
    asm("mov.b64 {%0, %1}, %2;" : "=f"(lo), "=f"(hi) : "l"(v));
}
__device__ __forceinline__ u64 fma2(u64 a, u64 b, u64 c) {
    u64 d;
    asm("fma.rn.f32x2 %0, %1, %2, %3;" : "=l"(d) : "l"(a), "l"(b), "l"(c));
    return d;
}

__global__ void k_zero() {
    int i = threadIdx.x;
    if (i < BB * NSLAB) { g_pcnt[i] = 0; g_qcnt[i] = 0; }
}

__device__ __forceinline__ int slab_of(float x) {
    int s = 0;
    #pragma unroll
    for (int k = 1; k <= 31; k++) s += (x >= cE[k]) ? 1 : 0;
    return s;
}

__global__ void k_scatter_p(const float* __restrict__ pnt) {
    int i = blockIdx.x * blockDim.x + threadIdx.x;   // 0 .. BB*MP-1
    int b = i >> 13;
    const float* p = pnt + (size_t)i * 3;
    float x = p[0], y = p[1], z = p[2];
    float c = -0.5f * (x * x + y * y + z * z);
    int s = slab_of(x);
    int pos = atomicAdd(&g_pcnt[b * NSLAB + s], 1);
    if (pos < PCAP)
        g_pts[(b * NSLAB + s) * PCAP + pos] = make_float4(x, y, z, c);
}

__global__ void k_scatter_q(const float* __restrict__ inp) {
    int i = blockIdx.x * blockDim.x + threadIdx.x;   // 0 .. BB*NQ-1
    int b = i >> 13, n = i & (NQ - 1);
    const float* q = inp + (size_t)i * 3;
    float x = q[0], y = q[1], z = q[2];
    int s = slab_of(x);
    int pos = atomicAdd(&g_qcnt[b * NSLAB + s], 1);
    if (pos < QCAP)
        g_qs[(b * NSLAB + s) * QCAP + pos] = make_float4(x, y, z, __int_as_float(n));
}

__global__ __launch_bounds__(TPB)
void k_nn(float* __restrict__ out) {
    __shared__ ulonglong2 sp[2 * MAXGRP];   // 8 KB

    const int b    = blockIdx.y;
    const int slab = blockIdx.x / NPART;
    const int part = blockIdx.x % NPART;
    const int t    = threadIdx.x;

    int nq = g_qcnt[b * NSLAB + slab];
    if (nq > QCAP) nq = QCAP;
    const int chunk = (nq + NPART - 1) / NPART;
    const int qs = part * chunk;
    const int qe = min(nq, qs + chunk);     // chunk <= 256 -> <= 2 queries/thread

    // Two queries per thread (second may be inactive).
    const int qi0 = qs + t;
    const int qi1 = qs + t + TPB;
    const bool act0 = qi0 < qe;
    const bool act1 = qi1 < qe;
    float4 q0 = act0 ? g_qs[(b * NSLAB + slab) * QCAP + qi0]
                     : make_float4(0.f, 0.f, 0.f, 0.f);
    float4 q1 = act1 ? g_qs[(b * NSLAB + slab) * QCAP + qi1]
                     : make_float4(0.f, 0.f, 0.f, 0.f);

    const u64 Qx0 = pack2(q0.x, q0.x), Qy0 = pack2(q0.y, q0.y), Qz0 = pack2(q0.z, q0.z);
    const u64 Qx1 = pack2(q1.x, q1.x), Qy1 = pack2(q1.y, q1.y), Qz1 = pack2(q1.z, q1.z);
    // Inactive queries: sq = 0, m = 0 -> d^2 = 0 -> always vote skip.
    const float sq0 = act0 ? (q0.x * q0.x + q0.y * q0.y + q0.z * q0.z) : 0.f;
    const float sq1 = act1 ? (q1.x * q1.x + q1.y * q1.y + q1.z * q1.z) : 0.f;
    float m0 = act0 ? -3.4e38f : 0.f;
    float m1 = act1 ? -3.4e38f : 0.f;

    // --- block-collective slab scan (dense FFMA2) ---
    auto scan = [&](int s) {
        int n = g_pcnt[b * NSLAB + s];
        if (n > PCAP) n = PCAP;
        const int ngrp = (n + 1) >> 1;
        const float4* base = g_pts + (b * NSLAB + s) * PCAP;

        __syncthreads();   // previous scan's smem reads complete
        for (int i = t; i < ngrp; i += TPB) {
            float4 p0 = base[2 * i];
            float4 p1 = (2 * i + 1 < n) ? base[2 * i + 1] : p0;  // dup if odd
            ulonglong2 a, bz;
            a.x  = pack2(p0.x, p1.x);  a.y  = pack2(p0.y, p1.y);
            bz.x = pack2(p0.z, p1.z);  bz.y = pack2(p0.w, p1.w);
            sp[2 * i]     = a;
            sp[2 * i + 1] = bz;
        }
        __syncthreads();

        #pragma unroll 2
        for (int g = 0; g < ngrp; g++) {
            ulonglong2 a  = sp[2 * g];
            ulonglong2 bz = sp[2 * g + 1];
            u64 t0 = fma2(a.x, Qx0, bz.y);
            u64 t1 = fma2(a.x, Qx1, bz.y);
            t0 = fma2(a.y, Qy0, t0);
            t1 = fma2(a.y, Qy1, t1);
            t0 = fma2(bz.x, Qz0, t0);
            t1 = fma2(bz.x, Qz1, t1);
            float lo, hi;
            unpack2(t0, lo, hi);
            m0 = fmaxf(m0, fmaxf(lo, hi));
            unpack2(t1, lo, hi);
            m1 = fmaxf(m1, fmaxf(lo, hi));
        }
    };

    scan(slab);

    int l = slab - 1, r = slab + 1;
    for (;;) {
        bool canL = false, canR = false;
        if (l >= 0) {   // block-uniform condition
            float e = cE[l + 1];
            float gl0 = q0.x - e, gl1 = q1.x - e;    // >= 0 for active lanes
            int skip = (gl0 * gl0 >= fmaf(-2.f, m0, sq0)) &&
                       (gl1 * gl1 >= fmaf(-2.f, m1, sq1));
            canL = !__syncthreads_and(skip);
        }
        if (r <= 31) {
            float e = cE[r];
            float gr0 = e - q0.x, gr1 = e - q1.x;
            int skip = (gr0 * gr0 >= fmaf(-2.f, m0, sq0)) &&
                       (gr1 * gr1 >= fmaf(-2.f, m1, sq1));
            canR = !__syncthreads_and(skip);
        }
        int s;
        if (canL && canR)
            s = ((cE[slab] - cE[l + 1]) <= (cE[r] - cE[slab + 1])) ? (l--) : (r++);
        else if (canL) s = l--;
        else if (canR) s = r++;
        else break;
        scan(s);
    }

    if (act0)
        out[b * NQ + __float_as_int(q0.w)] = fmaxf(fmaf(-2.f, m0, sq0), 0.f);
    if (act1)
        out[b * NQ + __float_as_int(q1.w)] = fmaxf(fmaf(-2.f, m1, sq1), 0.f);
}

extern "C" void kernel_launch(void* const* d_in, const int* in_sizes, int n_in,
                              void* d_out, int out_size) {
    const float* inp = (const float*)d_in[0];   // [B, N, 3] queries
    const float* pnt = (const float*)d_in[1];   // [B, M, 3] points
    float* out = (float*)d_out;                 // [B, N]

    k_zero<<<1, 128>>>();
    k_scatter_p<<<(BB * MP) / TPB, TPB>>>(pnt);
    k_scatter_q<<<(BB * NQ) / TPB, TPB>>>(inp);
    k_nn<<<dim3(NSLAB * NPART, BB), TPB>>>(out);
}

// round 14
// speedup vs baseline: 11.5739x; 2.5900x over previous
#include <cuda_runtime.h>
#include <cstdint>

// DistanceLoss: out[b,n] = min_m ||input[b,n,:] - point[b,m,:]||^2
// B=4, N=8192, M=8192, D=3 (float32).
//
// R15: dense FFMA2 brute force (R10, best known) with overhead trims:
//  - init kernel replaced by cudaMemsetAsync(d_out, 0x7F): captured as a graph
//    memset node. 0x7F7F7F7F = 3.39e38f > any clamped result, both as float
//    and as unsigned bits, so the unsigned atomicMin combine remains exact.
//  - group loop unroll 4 (more independent FFMA2 in the scheduler window).
//  smem per 2-point group g (pair-packed, no duplication):
//    sp[2g]   = { (p0x,p1x), (p0y,p1y) }
//    sp[2g+1] = { (p0z,p1z), (c0,c1) },  c = -0.5*|p|^2
//  Queries duplicated in registers as (qk,qk); FFMA2 = 1 query x 2 points.
//  Per group per warp: 2 LDS.128 + 24 FFMA2 + 16 FMNMX serve 512 pairs.
//  d2 = |q|^2 - 2*max_m(p.q - 0.5|p|^2), clamped at 0 (results >= 0).
//  MSPLIT=32, MCH=256 exact: 1024 uniform blocks, launch_bounds(128,7).

#define BB      4
#define NQ      8192
#define MP      8192
#define MSPLIT  32
#define MCH     (MP / MSPLIT)    // 256 points per chunk (exact)
#define NGRP    (MCH / 2)        // 128 groups -> 4096 B smem
#define TPB     128
#define QPT     8                // queries per thread
#define QPB     (TPB * QPT)      // 1024 queries per block
#define NBLK    (NQ / QPB)       // 8

typedef unsigned long long u64;

__device__ __forceinline__ u64 pack2(float lo, float hi) {
    u64 r;
    asm("mov.b64 %0, {%1, %2};" : "=l"(r) : "f"(lo), "f"(hi));
    return r;
}
__device__ __forceinline__ void unpack2(u64 v, float& lo, float& hi) {
    asm("mov.b64 {%0, %1}, %2;" : "=f"(lo), "=f"(hi) : "l"(v));
}
__device__ __forceinline__ u64 fma2(u64 a, u64 b, u64 c) {
    u64 d;
    asm("fma.rn.f32x2 %0, %1, %2, %3;" : "=l"(d) : "l"(a), "l"(b), "l"(c));
    return d;
}

__global__ __launch_bounds__(TPB, 7)
void dl_nn_kernel(const float* __restrict__ inp,
                  const float* __restrict__ pnt,
                  float* __restrict__ out) {
    __shared__ ulonglong2 sp[2 * NGRP];   // 4 KB

    const int b    = blockIdx.y;
    const int nblk = blockIdx.x / MSPLIT;
    const int mc   = blockIdx.x % MSPLIT;
    const int t    = threadIdx.x;

    // Fill smem: group i = points (mc*MCH + 2i, mc*MCH + 2i + 1), pair-packed.
    const float* pbase = pnt + ((size_t)b * MP + mc * MCH) * 3;
    for (int i = t; i < NGRP; i += TPB) {
        const float* p0 = pbase + 6 * i;
        float p0x = p0[0], p0y = p0[1], p0z = p0[2];
        float p1x = p0[3], p1y = p0[4], p1z = p0[5];
        float c0 = -0.5f * (p0x * p0x + p0y * p0y + p0z * p0z);
        float c1 = -0.5f * (p1x * p1x + p1y * p1y + p1z * p1z);
        ulonglong2 a, bb2;
        a.x  = pack2(p0x, p1x);  a.y  = pack2(p0y, p1y);
        bb2.x = pack2(p0z, p1z); bb2.y = pack2(c0, c1);
        sp[2 * i]     = a;
        sp[2 * i + 1] = bb2;
    }
    __syncthreads();

    // Load 8 queries (coalesced per k), duplicate into packed pairs (qk,qk).
    const int nbase = nblk * QPB;
    u64 Qx[QPT], Qy[QPT], Qz[QPT];
    #pragma unroll
    for (int k = 0; k < QPT; k++) {
        const float* q = inp + ((size_t)b * NQ + nbase + t + k * TPB) * 3;
        float qx = q[0], qy = q[1], qz = q[2];
        Qx[k] = pack2(qx, qx);
        Qy[k] = pack2(qy, qy);
        Qz[k] = pack2(qz, qz);
    }

    const float NEG = -3.402823466e38f;
    float m[QPT];
    #pragma unroll
    for (int k = 0; k < QPT; k++) m[k] = NEG;

    #pragma unroll 4
    for (int g = 0; g < NGRP; g++) {
        ulonglong2 a  = sp[2 * g];       // (p0x,p1x),(p0y,p1y)
        ulonglong2 bz = sp[2 * g + 1];   // (p0z,p1z),(c0,c1)

        u64 tt[QPT];
        #pragma unroll
        for (int k = 0; k < QPT; k++) tt[k] = fma2(a.x, Qx[k], bz.y);
        #pragma unroll
        for (int k = 0; k < QPT; k++) tt[k] = fma2(a.y, Qy[k], tt[k]);
        #pragma unroll
        for (int k = 0; k < QPT; k++) tt[k] = fma2(bz.x, Qz[k], tt[k]);

        #pragma unroll
        for (int k = 0; k < QPT; k++) {
            float lo, hi;
            unpack2(tt[k], lo, hi);
            m[k] = fmaxf(m[k], fmaxf(lo, hi));
        }
    }

    #pragma unroll
    for (int k = 0; k < QPT; k++) {
        float qx, qy, qz, dummy;
        unpack2(Qx[k], qx, dummy);
        unpack2(Qy[k], qy, dummy);
        unpack2(Qz[k], qz, dummy);
        float sq = qx * qx + qy * qy + qz * qz;
        float v = fmaxf(fmaf(-2.0f, m[k], sq), 0.0f);
        atomicMin(reinterpret_cast<unsigned int*>(
                      &out[(size_t)b * NQ + nbase + t + k * TPB]),
                  __float_as_uint(v));
    }
}

extern "C" void kernel_launch(void* const* d_in, const int* in_sizes, int n_in,
                              void* d_out, int out_size) {
    const float* inp = (const float*)d_in[0];   // [B, N, 3]
    const float* pnt = (const float*)d_in[1];   // [B, M, 3]
    float* out = (float*)d_out;                 // [B, N]

    // Init output to 0x7F7F7F7F (3.39e38f): graph-capturable memset node.
    // Correctness: larger than any clamped result both as float and as uint
    // bits, so the atomicMin-on-bits combine below is exact.
    cudaMemsetAsync(out, 0x7F, (size_t)out_size * sizeof(float));

    dim3 grid(NBLK * MSPLIT, BB);
    dl_nn_kernel<<<grid, TPB>>>(inp, pnt, out);
}